// round 3
// baseline (speedup 1.0000x reference)
#include <cuda_runtime.h>

// VDEmbedding: out[t, :] = mask[x[t]] * weight[x[t], :], zero at pad (idx==0).
// x: [65536] int64 OR int32 (auto-detected), weight: [128000,128] f32,
// mask: [128000] f32, out: [65536,128] f32.
//
// R3: 8 tokens/warp. Lanes 0..7 load idx+mask (1 coalesced load each),
// shfl-broadcast to the warp, then 8 independent 512B row gathers in flight.
// Indices read via the low 32-bit word (ids < 2^31) -> one code path.

#define EMBED_V4 32     // 128 floats = 32 float4 per row
#define TOK_PER_WARP 8

__device__ int g_idx_shift;   // 1 if indices are int64 (stride 2 words), 0 if int32

// int64 data => all odd 32-bit words are zero. int32 data => odd words are
// random token ids; P(32 consecutive odd words all zero) ~ (1/128000)^32 ~ 0.
// Reads stay in the first 256 B, valid for both layouts.
__global__ void detect_idx_dtype_kernel(const unsigned int* __restrict__ xw) {
    unsigned int v = xw[2 * threadIdx.x + 1];
    v = __reduce_or_sync(0xffffffffu, v);
    if (threadIdx.x == 0) g_idx_shift = (v == 0u) ? 1 : 0;
}

__global__ __launch_bounds__(256) void vdembed_kernel(
    const unsigned int* __restrict__ x32,  // raw index words
    const float4*       __restrict__ w4,   // weight as [V, 32] float4
    const float*        __restrict__ mask,
    float4*             __restrict__ out4, // out as [T, 32] float4
    int n_tokens)
{
    const int warp = (int)((blockIdx.x * blockDim.x + threadIdx.x) >> 5);
    const int lane = threadIdx.x & 31;
    const int t0   = warp * TOK_PER_WARP;
    if (t0 >= n_tokens) return;

    const int shift = g_idx_shift;   // uniform load, L2-resident

    // ---- lanes 0..7: one idx load + one mask load each ----
    unsigned int myidx = 0u;
    float        mysc  = 0.0f;
    if (lane < TOK_PER_WARP) {
        const int t = t0 + lane;
        if (t < n_tokens) {
            myidx = x32[(size_t)t << shift];        // low word == token id
            mysc  = (myidx == 0u) ? 0.0f : __ldg(&mask[myidx]);
        }
    }

    // ---- broadcast indices first (gathers depend only on these) ----
    unsigned int id[TOK_PER_WARP];
#pragma unroll
    for (int t = 0; t < TOK_PER_WARP; t++)
        id[t] = __shfl_sync(0xffffffffu, myidx, t);

    // ---- 8 independent 512B row gathers in flight ----
    float4 v[TOK_PER_WARP];
#pragma unroll
    for (int t = 0; t < TOK_PER_WARP; t++)
        v[t] = __ldg(&w4[(size_t)id[t] * EMBED_V4 + lane]);

    // ---- scales (mask loads overlap the gathers) ----
    float sc[TOK_PER_WARP];
#pragma unroll
    for (int t = 0; t < TOK_PER_WARP; t++)
        sc[t] = __shfl_sync(0xffffffffu, mysc, t);

#pragma unroll
    for (int t = 0; t < TOK_PER_WARP; t++) {
        v[t].x *= sc[t]; v[t].y *= sc[t]; v[t].z *= sc[t]; v[t].w *= sc[t];
    }

    // ---- streaming stores: output has zero reuse; keep table in L2 ----
    float4* o = out4 + (size_t)t0 * EMBED_V4 + lane;
    if (t0 + TOK_PER_WARP <= n_tokens) {
#pragma unroll
        for (int t = 0; t < TOK_PER_WARP; t++)
            __stcs(o + (size_t)t * EMBED_V4, v[t]);
    } else {
#pragma unroll
        for (int t = 0; t < TOK_PER_WARP; t++)
            if (t0 + t < n_tokens) __stcs(o + (size_t)t * EMBED_V4, v[t]);
    }
}

extern "C" void kernel_launch(void* const* d_in, const int* in_sizes, int n_in,
                              void* d_out, int out_size) {
    const unsigned int* x   = (const unsigned int*)d_in[0]; // [B*S] i64 or i32
    const float*        w   = (const float*)d_in[1];        // [V, 128]
    const float*        msk = (const float*)d_in[2];        // [V]
    float*              out = (float*)d_out;                // [B*S, 128]

    const int n_tokens = in_sizes[0];

    detect_idx_dtype_kernel<<<1, 32>>>(x);

    const int warps   = (n_tokens + TOK_PER_WARP - 1) / TOK_PER_WARP;
    const int threads = 256;
    const int blocks  = (warps * 32 + threads - 1) / threads;
    vdembed_kernel<<<blocks, threads>>>(
        x, (const float4*)w, msk, (float4*)out, n_tokens);
}